// round 3
// baseline (speedup 1.0000x reference)
#include <cuda_runtime.h>

#define WDIM  64
#define SDIM  512
#define C8    64
#define XST   516   // Xs row stride
#define FGST  132
#define AST   68

__device__ float g_inv_sigma;
// fragment-packed, tf32-pre-rounded weight copies
__device__ float g_whP [262144];  // wh  [512x512]
__device__ float g_wsnP[262144];  // wsn [512x512]
__device__ float g_fgP [65536];   // [wf|wg] packed

__device__ __forceinline__ unsigned f2tf(float f) {
    unsigned r;
    asm("cvt.rna.tf32.f32 %0, %1;" : "=r"(r) : "f"(f));
    return r;
}
__device__ __forceinline__ float rndtf(float f) { return __uint_as_float(f2tf(f)); }
__device__ __forceinline__ unsigned bits(float f) { return __float_as_uint(f); }

__device__ __forceinline__ void mma_tf32(float* c,
                                         unsigned a0, unsigned a1, unsigned a2, unsigned a3,
                                         unsigned b0, unsigned b1) {
    asm volatile(
        "mma.sync.aligned.m16n8k8.row.col.f32.tf32.tf32.f32 "
        "{%0,%1,%2,%3}, {%4,%5,%6,%7}, {%8,%9}, {%0,%1,%2,%3};\n"
        : "+f"(c[0]), "+f"(c[1]), "+f"(c[2]), "+f"(c[3])
        : "r"(a0), "r"(a1), "r"(a2), "r"(a3), "r"(b0), "r"(b1));
}

// ---------------------------------------------------------------------------
// init kernel: blocks 0..511 pack+round weights; block 512 computes sigma.
// ---------------------------------------------------------------------------
__global__ __launch_bounds__(512)
void init_kernel(const float* __restrict__ wf, const float* __restrict__ wg,
                 const float* __restrict__ wh, const float* __restrict__ wsn,
                 const float* __restrict__ usn) {
    if (blockIdx.x < 512) {
        int i = blockIdx.x * 512 + threadIdx.x;   // 0..262143
        {
            int j = i & 3, l = (i >> 2) & 31, h = (i >> 7) & 1, r = (i >> 8) & 1;
            int ng = (i >> 9) & 7, ks = i >> 12;
            int row = ks * 8 + (l & 3) + r * 4;
            int col = ng * 64 + (h * 4 + j) * 8 + (l >> 2);
            g_whP[i]  = rndtf(wh [(size_t)row * SDIM + col]);
            g_wsnP[i] = rndtf(wsn[(size_t)row * SDIM + col]);
        }
        if (i < 65536) {
            int j = i & 3, l = (i >> 2) & 31, r = (i >> 7) & 1;
            int ng = (i >> 8) & 3, ks = i >> 10;
            int row = ks * 8 + (l & 3) + r * 4;
            int col = ng * 32 + j * 8 + (l >> 2);
            g_fgP[i] = rndtf(col < 64 ? wf[(size_t)row * C8 + col]
                                      : wg[(size_t)row * C8 + col - 64]);
        }
        return;
    }
    // ---- sigma (one block) ----
    __shared__ float us[512];
    __shared__ float vs[512];
    __shared__ float red[17];
    int tid = threadIdx.x, wid = tid >> 5, lane = tid & 31;
    us[tid] = usn[tid];
    __syncthreads();

    float q = 0.f;
    for (int rr = 0; rr < 32; rr++) {
        int row = wid * 32 + rr;
        const float4* wr = (const float4*)(wsn + (size_t)row * SDIM);
        const float4* ur = (const float4*)us;
        float s = 0.f;
        #pragma unroll
        for (int i = 0; i < 4; i++) {
            float4 w = wr[lane + i * 32], u = ur[lane + i * 32];
            s += w.x * u.x + w.y * u.y + w.z * u.z + w.w * u.w;
        }
        #pragma unroll
        for (int o = 16; o; o >>= 1) s += __shfl_xor_sync(0xffffffffu, s, o);
        if (lane == 0) { vs[row] = s; q += s * s; }
    }
    if (lane == 0) red[wid] = q;
    __syncthreads();
    if (tid == 0) {
        float z = 0.f;
        for (int i = 0; i < 16; i++) z += red[i];
        red[16] = 1.f / (sqrtf(z) + 1e-12f);
    }
    __syncthreads();
    float inv_nv = red[16];
    __syncthreads();

    float t0 = 0.f, t1 = 0.f, t2 = 0.f, t3 = 0.f;
    for (int i = 0; i < SDIM; i += 4) {
        t0 += vs[i + 0] * wsn[(size_t)(i + 0) * SDIM + tid];
        t1 += vs[i + 1] * wsn[(size_t)(i + 1) * SDIM + tid];
        t2 += vs[i + 2] * wsn[(size_t)(i + 2) * SDIM + tid];
        t3 += vs[i + 3] * wsn[(size_t)(i + 3) * SDIM + tid];
    }
    float tj = ((t0 + t1) + (t2 + t3)) * inv_nv;
    float q2 = tj * tj;
    #pragma unroll
    for (int o = 16; o; o >>= 1) q2 += __shfl_xor_sync(0xffffffffu, q2, o);
    if (lane == 0) red[wid] = q2;
    __syncthreads();
    if (tid == 0) {
        float z = 0.f;
        for (int i = 0; i < 16; i++) z += red[i];
        float nt = sqrtf(z);
        g_inv_sigma = (nt + 1e-12f) / z;
    }
}

// ---------------------------------------------------------------------------
// Pipelined MMA block: acc[2][8][4] += A(64xK) @ Wpacked, NKS k-steps.
// wp points at this warp's fragment base for the FIRST k-step (lane folded in).
// Bc[4] holds the pre-loaded first k-step fragments (caller prefetches them
// early so the first L2 access is already in flight).
// Per k-step stride in uint4 units: 8*4*32 = 1024 (16 KB).
// ---------------------------------------------------------------------------
template <int STRIDE, int NKS>
__device__ __forceinline__ void mma_block_pf(float (&acc)[2][8][4],
                                             const float* __restrict__ A,
                                             const uint4* __restrict__ wp,
                                             uint4 (&Bc)[4],
                                             int mg, int g, int t) {
    #pragma unroll 2
    for (int ks = 0; ks < NKS; ks++) {
        uint4 Bn[4];
        if (ks + 1 < NKS) {
            const uint4* p = wp + (size_t)(ks + 1) * 1024;
            Bn[0] = p[0]; Bn[1] = p[32]; Bn[2] = p[64]; Bn[3] = p[96];
        }
        unsigned b0[8] = {Bc[0].x, Bc[0].y, Bc[0].z, Bc[0].w,
                          Bc[1].x, Bc[1].y, Bc[1].z, Bc[1].w};
        unsigned b1[8] = {Bc[2].x, Bc[2].y, Bc[2].z, Bc[2].w,
                          Bc[3].x, Bc[3].y, Bc[3].z, Bc[3].w};
        int k = ks * 8;
        #pragma unroll
        for (int mi = 0; mi < 2; mi++) {
            int r = mg * 32 + mi * 16 + g;
            unsigned a0 = bits(A[r * STRIDE + k + t]);
            unsigned a1 = bits(A[(r + 8) * STRIDE + k + t]);
            unsigned a2 = bits(A[r * STRIDE + k + t + 4]);
            unsigned a3 = bits(A[(r + 8) * STRIDE + k + t + 4]);
            #pragma unroll
            for (int nj = 0; nj < 8; nj++)
                mma_tf32(acc[mi][nj], a0, a1, a2, a3, b0[nj], b1[nj]);
        }
        Bc[0] = Bn[0]; Bc[1] = Bn[1]; Bc[2] = Bn[2]; Bc[3] = Bn[3];
    }
}

// ---------------------------------------------------------------------------
extern __shared__ float smf[];

__global__ __launch_bounds__(512, 1)
void fused_kernel(const float* __restrict__ x,
                  const float* __restrict__ bf, const float* __restrict__ bg,
                  const float* __restrict__ bh,
                  const float* __restrict__ gamma,
                  const float* __restrict__ ln1g, const float* __restrict__ ln1b,
                  const float* __restrict__ ln2g, const float* __restrict__ ln2b,
                  float* __restrict__ out) {
    float* Xs     = smf;                    // 64 x 516
    float* FGs    = Xs + 64 * XST;          // 64 x 132
    float* ATTs   = FGs + 64 * FGST;        // 64 x 68
    float* AXs    = ATTs + 64 * AST;        // 2 x (64 x 68)
    float* rowsum = AXs + 2 * 64 * AST;     // 64
    float* stats  = rowsum + 64;            // 128

    const int tid  = threadIdx.x;
    const int wid  = tid >> 5;
    const int lane = tid & 31;
    const int g    = lane >> 2;
    const int t    = lane & 3;
    const size_t base = (size_t)blockIdx.x * (WDIM * SDIM);

    const int mg1 = wid & 3;
    const int ng1 = wid >> 2;

    // GEMM1 first-fragment prefetch (independent of Xs)
    const uint4* fgp0 = reinterpret_cast<const uint4*>(g_fgP) + (size_t)(ng1 * 2) * 32 + lane;
    uint4 FB0 = fgp0[0];
    uint4 FB1 = fgp0[32];

    // ---- load X, pre-rounded to tf32 ----
    for (int i = tid; i < WDIM * SDIM / 4; i += 512) {
        float4 v = ((const float4*)(x + base))[i];
        int r = i >> 7;
        int c = (i & 127) * 4;
        float* p = &Xs[r * XST + c];
        p[0] = rndtf(v.x); p[1] = rndtf(v.y); p[2] = rndtf(v.z); p[3] = rndtf(v.w);
    }
    __syncthreads();

    // ---- GEMM1: [F|G] = X @ [Wf|Wg] + bias   (pipelined) ----
    {
        float acc1[4][4];
        #pragma unroll
        for (int nj = 0; nj < 4; nj++)
            #pragma unroll
            for (int c = 0; c < 4; c++) acc1[nj][c] = 0.f;

        const int rA = mg1 * 16 + g;
        #pragma unroll 2
        for (int ks = 0; ks < 64; ks++) {
            uint4 N0, N1;
            if (ks + 1 < 64) {
                const uint4* p = fgp0 + (size_t)(ks + 1) * 256;   // 4*2*32 uint4/ks
                N0 = p[0]; N1 = p[32];
            }
            unsigned b0[4] = {FB0.x, FB0.y, FB0.z, FB0.w};
            unsigned b1[4] = {FB1.x, FB1.y, FB1.z, FB1.w};
            int k = ks * 8;
            unsigned a0 = bits(Xs[rA * XST + k + t]);
            unsigned a1 = bits(Xs[(rA + 8) * XST + k + t]);
            unsigned a2 = bits(Xs[rA * XST + k + t + 4]);
            unsigned a3 = bits(Xs[(rA + 8) * XST + k + t + 4]);
            #pragma unroll
            for (int nj = 0; nj < 4; nj++)
                mma_tf32(acc1[nj], a0, a1, a2, a3, b0[nj], b1[nj]);
            FB0 = N0; FB1 = N1;
        }
        #pragma unroll
        for (int nj = 0; nj < 4; nj++) {
            int cg = ng1 * 32 + nj * 8 + 2 * t;
            float bias0 = (cg < 64) ? bf[cg] : bg[cg - 64];
            float bias1 = (cg + 1 < 64) ? bf[cg + 1] : bg[cg + 1 - 64];
            FGs[rA * FGST + cg]           = rndtf(acc1[nj][0] + bias0);
            FGs[rA * FGST + cg + 1]       = rndtf(acc1[nj][1] + bias1);
            FGs[(rA + 8) * FGST + cg]     = rndtf(acc1[nj][2] + bias0);
            FGs[(rA + 8) * FGST + cg + 1] = rndtf(acc1[nj][3] + bias1);
        }
    }
    __syncthreads();

    const int mhalf = wid >> 3;
    const int n8    = (wid & 7) * 8;

    // ---- GEMM2: ATT = sigmoid(F @ G^T) ----
    {
        float acc2[2][4];
        #pragma unroll
        for (int mi = 0; mi < 2; mi++)
            #pragma unroll
            for (int c = 0; c < 4; c++) acc2[mi][c] = 0.f;

        #pragma unroll
        for (int k = 0; k < 64; k += 8) {
            unsigned b0 = bits(FGs[(n8 + g) * FGST + 64 + k + t]);
            unsigned b1 = bits(FGs[(n8 + g) * FGST + 64 + k + t + 4]);
            #pragma unroll
            for (int mi = 0; mi < 2; mi++) {
                int r = (mhalf * 2 + mi) * 16 + g;
                unsigned a0 = bits(FGs[r * FGST + k + t]);
                unsigned a1 = bits(FGs[(r + 8) * FGST + k + t]);
                unsigned a2 = bits(FGs[r * FGST + k + t + 4]);
                unsigned a3 = bits(FGs[(r + 8) * FGST + k + t + 4]);
                mma_tf32(acc2[mi], a0, a1, a2, a3, b0, b1);
            }
        }
        #pragma unroll
        for (int mi = 0; mi < 2; mi++) {
            int r = (mhalf * 2 + mi) * 16 + g;
            ATTs[r * AST + n8 + 2 * t]           = rndtf(1.f / (1.f + __expf(-acc2[mi][0])));
            ATTs[r * AST + n8 + 2 * t + 1]       = rndtf(1.f / (1.f + __expf(-acc2[mi][1])));
            ATTs[(r + 8) * AST + n8 + 2 * t]     = rndtf(1.f / (1.f + __expf(-acc2[mi][2])));
            ATTs[(r + 8) * AST + n8 + 2 * t + 1] = rndtf(1.f / (1.f + __expf(-acc2[mi][3])));
        }
    }
    __syncthreads();

    if (tid < 64) {
        float s = 0.f;
        for (int v = 0; v < 64; v++) s += ATTs[tid * AST + v];
        rowsum[tid] = s;
    }

    // ---- GEMM3+4 fused: ATTN = (ATT @ X) @ Wh   (weights prefetched under GEMM3) ----
    const int mg = wid & 1;
    const int ng = wid >> 1;
    const uint4* whpW  = reinterpret_cast<const uint4*>(g_whP)  + (size_t)(ng * 4) * 32 + lane;
    const uint4* wsnpW = reinterpret_cast<const uint4*>(g_wsnP) + (size_t)(ng * 4) * 32 + lane;

    float acc[2][8][4];
    #pragma unroll
    for (int mi = 0; mi < 2; mi++)
        #pragma unroll
        for (int nj = 0; nj < 8; nj++)
            #pragma unroll
            for (int c = 0; c < 4; c++) acc[mi][nj][c] = 0.f;

    for (int kc = 0; kc < 8; kc++) {
        const int cb = kc * 64;
        float* AXb = AXs + (kc & 1) * 64 * AST;
        const uint4* wp = whpW + (size_t)(kc * 8) * 1024;

        // prefetch first weight k-step of this chunk NOW (hidden by GEMM3)
        uint4 Bc[4];
        Bc[0] = wp[0]; Bc[1] = wp[32]; Bc[2] = wp[64]; Bc[3] = wp[96];

        float axc[2][4];
        #pragma unroll
        for (int mi = 0; mi < 2; mi++)
            #pragma unroll
            for (int c = 0; c < 4; c++) axc[mi][c] = 0.f;

        #pragma unroll
        for (int k = 0; k < 64; k += 8) {
            unsigned b0 = bits(Xs[(k + t) * XST + cb + n8 + g]);
            unsigned b1 = bits(Xs[(k + t + 4) * XST + cb + n8 + g]);
            #pragma unroll
            for (int mi = 0; mi < 2; mi++) {
                int r = (mhalf * 2 + mi) * 16 + g;
                unsigned a0 = bits(ATTs[r * AST + k + t]);
                unsigned a1 = bits(ATTs[(r + 8) * AST + k + t]);
                unsigned a2 = bits(ATTs[r * AST + k + t + 4]);
                unsigned a3 = bits(ATTs[(r + 8) * AST + k + t + 4]);
                mma_tf32(axc[mi], a0, a1, a2, a3, b0, b1);
            }
        }
        #pragma unroll
        for (int mi = 0; mi < 2; mi++) {
            int r = (mhalf * 2 + mi) * 16 + g;
            AXb[r * AST + n8 + 2 * t]           = rndtf(axc[mi][0]);
            AXb[r * AST + n8 + 2 * t + 1]       = rndtf(axc[mi][1]);
            AXb[(r + 8) * AST + n8 + 2 * t]     = rndtf(axc[mi][2]);
            AXb[(r + 8) * AST + n8 + 2 * t + 1] = rndtf(axc[mi][3]);
        }
        __syncthreads();

        mma_block_pf<AST, 8>(acc, AXb, wp, Bc, mg, g, t);
    }

    // ---- epilogue 1: Xs = gamma*(attn + rowsum*bh)  (x added in LN1 pass) ----
    {
        float gam = gamma[0];
        #pragma unroll
        for (int mi = 0; mi < 2; mi++) {
            int r0 = mg * 32 + mi * 16 + g, r1 = r0 + 8;
            float rs0 = rowsum[r0], rs1 = rowsum[r1];
            #pragma unroll
            for (int nj = 0; nj < 8; nj++) {
                int c0 = ng * 64 + nj * 8 + 2 * t;
                float bh0 = bh[c0], bh1 = bh[c0 + 1];
                Xs[r0 * XST + c0]     = gam * (acc[mi][nj][0] + rs0 * bh0);
                Xs[r0 * XST + c0 + 1] = gam * (acc[mi][nj][1] + rs0 * bh1);
                Xs[r1 * XST + c0]     = gam * (acc[mi][nj][2] + rs1 * bh0);
                Xs[r1 * XST + c0 + 1] = gam * (acc[mi][nj][3] + rs1 * bh1);
            }
        }
    }
    __syncthreads();

    // ---- LN1 pass1: add residual x (re-read), accumulate stats ----
    {
        int row = tid >> 3, j0 = tid & 7;
        const float4* xr = (const float4*)(x + base + (size_t)row * SDIM);
        float4* Xr = (float4*)(Xs + row * XST);
        float s = 0.f, sq = 0.f;
        #pragma unroll
        for (int i = 0; i < 16; i++) {
            int c4 = j0 + i * 8;
            float4 v = Xr[c4];
            float4 xv = xr[c4];
            v.x += xv.x; v.y += xv.y; v.z += xv.z; v.w += xv.w;
            Xr[c4] = v;
            s  += (v.x + v.y) + (v.z + v.w);
            sq += (v.x * v.x + v.y * v.y) + (v.z * v.z + v.w * v.w);
        }
        #pragma unroll
        for (int o = 1; o <= 4; o <<= 1) {
            s  += __shfl_xor_sync(0xffffffffu, s, o);
            sq += __shfl_xor_sync(0xffffffffu, sq, o);
        }
        if (j0 == 0) {
            float mean = s * (1.f / SDIM);
            float var  = sq * (1.f / SDIM) - mean * mean;
            stats[row * 2]     = mean;
            stats[row * 2 + 1] = rsqrtf(var + 1e-6f);
        }
    }
    __syncthreads();

    // GEMM5 first-fragment prefetch (hidden by LN1 pass2)
    uint4 Bc5[4];
    Bc5[0] = wsnpW[0]; Bc5[1] = wsnpW[32]; Bc5[2] = wsnpW[64]; Bc5[3] = wsnpW[96];

    // ---- LN1 pass2: normalize, pre-round (feeds GEMM5 only) ----
    {
        int row = tid >> 3, j0 = tid & 7;
        float mean = stats[row * 2], rstd = stats[row * 2 + 1];
        float4* Xr = (float4*)(Xs + row * XST);
        #pragma unroll
        for (int i = 0; i < 16; i++) {
            int c4 = j0 + i * 8;
            float4 v = Xr[c4];
            float4 gv = ((const float4*)ln1g)[c4];
            float4 bv = ((const float4*)ln1b)[c4];
            v.x = rndtf((v.x - mean) * rstd * gv.x + bv.x);
            v.y = rndtf((v.y - mean) * rstd * gv.y + bv.y);
            v.z = rndtf((v.z - mean) * rstd * gv.z + bv.z);
            v.w = rndtf((v.w - mean) * rstd * gv.w + bv.w);
            Xr[c4] = v;
        }
    }
    __syncthreads();

    // ---- GEMM5: Y = out1 @ Wsn ----
    #pragma unroll
    for (int mi = 0; mi < 2; mi++)
        #pragma unroll
        for (int nj = 0; nj < 8; nj++)
            #pragma unroll
            for (int c = 0; c < 4; c++) acc[mi][nj][c] = 0.f;

    mma_block_pf<XST, 64>(acc, Xs, wsnpW, Bc5, mg, g, t);
    __syncthreads();

    // ---- epilogue 2: relu(acc/sigma) -> Xs ----
    {
        float invsig = g_inv_sigma;
        #pragma unroll
        for (int mi = 0; mi < 2; mi++) {
            int r0 = mg * 32 + mi * 16 + g, r1 = r0 + 8;
            #pragma unroll
            for (int nj = 0; nj < 8; nj++) {
                int c0 = ng * 64 + nj * 8 + 2 * t;
                Xs[r0 * XST + c0]     = fmaxf(acc[mi][nj][0] * invsig, 0.f);
                Xs[r0 * XST + c0 + 1] = fmaxf(acc[mi][nj][1] * invsig, 0.f);
                Xs[r1 * XST + c0]     = fmaxf(acc[mi][nj][2] * invsig, 0.f);
                Xs[r1 * XST + c0 + 1] = fmaxf(acc[mi][nj][3] * invsig, 0.f);
            }
        }
    }
    __syncthreads();

    // ---- LN2 pass1 ----
    {
        int row = tid >> 3, j0 = tid & 7;
        const float4* Xr = (const float4*)(Xs + row * XST);
        float s = 0.f, sq = 0.f;
        #pragma unroll
        for (int i = 0; i < 16; i++) {
            float4 v = Xr[j0 + i * 8];
            s  += (v.x + v.y) + (v.z + v.w);
            sq += (v.x * v.x + v.y * v.y) + (v.z * v.z + v.w * v.w);
        }
        #pragma unroll
        for (int o = 1; o <= 4; o <<= 1) {
            s  += __shfl_xor_sync(0xffffffffu, s, o);
            sq += __shfl_xor_sync(0xffffffffu, sq, o);
        }
        if (j0 == 0) {
            float mean = s * (1.f / SDIM);
            float var  = sq * (1.f / SDIM) - mean * mean;
            stats[row * 2]     = mean;
            stats[row * 2 + 1] = rsqrtf(var + 1e-6f);
        }
    }
    __syncthreads();
    // ---- LN2 pass2 -> global out ----
    {
        int row = tid >> 3, j0 = tid & 7;
        float mean = stats[row * 2], rstd = stats[row * 2 + 1];
        const float4* Xr = (const float4*)(Xs + row * XST);
        float4* orow = (float4*)(out + base + (size_t)row * SDIM);
        #pragma unroll
        for (int i = 0; i < 16; i++) {
            int c4 = j0 + i * 8;
            float4 v = Xr[c4];
            float4 gv = ((const float4*)ln2g)[c4];
            float4 bv = ((const float4*)ln2b)[c4];
            v.x = (v.x - mean) * rstd * gv.x + bv.x;
            v.y = (v.y - mean) * rstd * gv.y + bv.y;
            v.z = (v.z - mean) * rstd * gv.z + bv.z;
            v.w = (v.w - mean) * rstd * gv.w + bv.w;
            orow[c4] = v;
        }
    }
}

// ---------------------------------------------------------------------------
extern "C" void kernel_launch(void* const* d_in, const int* in_sizes, int n_in,
                              void* d_out, int out_size) {
    (void)in_sizes; (void)n_in; (void)out_size;
    const float* x    = (const float*)d_in[0];
    const float* wf   = (const float*)d_in[1];
    const float* bf   = (const float*)d_in[2];
    const float* wg   = (const float*)d_in[3];
    const float* bg   = (const float*)d_in[4];
    const float* wh   = (const float*)d_in[5];
    const float* bh   = (const float*)d_in[6];
    const float* gam  = (const float*)d_in[7];
    const float* ln1g = (const float*)d_in[8];
    const float* ln1b = (const float*)d_in[9];
    const float* wsn  = (const float*)d_in[10];
    const float* usn  = (const float*)d_in[11];
    const float* ln2g = (const float*)d_in[12];
    const float* ln2b = (const float*)d_in[13];
    float* out = (float*)d_out;

    init_kernel<<<513, 512>>>(wf, wg, wh, wsn, usn);

    const int smem_bytes = (64 * XST + 64 * FGST + 64 * AST + 2 * 64 * AST + 64 + 128) * 4;
    cudaFuncSetAttribute(fused_kernel, cudaFuncAttributeMaxDynamicSharedMemorySize, smem_bytes);
    fused_kernel<<<1024, 512, smem_bytes>>>(x, bf, bg, bh, gam,
                                            ln1g, ln1b, ln2g, ln2b, out);
}